// round 15
// baseline (speedup 1.0000x reference)
#include <cuda_runtime.h>
#include <cuda_bf16.h>
#include <stdint.h>

#define NN 4096
#define NB 16
#define ND 64

// GEMM tiling: C[4096,1024] = W[4096,4096] @ Xt^T, Xt[n=b*64+d][k]
#define BM 256
#define BN 128
#define BK 64
#define STAGES 4
#define KT (NN / BK)                 // 64
#define ASTR 72                      // padded row stride (elems): 144B, %16==0
#define A_TILE_B (BM * ASTR * 2)     // 36864
#define B_TILE_B (BN * ASTR * 2)     // 18432
#define STAGE_B (A_TILE_B + B_TILE_B) // 55296
#define SMEM_B (STAGES * STAGE_B)    // 221184 (occ 1)

// ---------------- scratch (device globals: allocation-free) ----------------
static __device__ __align__(16) __nv_bfloat16 g_Wbf[(size_t)NN * NN];        // 32 MB, diag=0
static __device__ __align__(16) __nv_bfloat16 g_Xt[(size_t)NB * ND * NN];    // 8 MB, [b*64+d][k]
static __device__ __align__(16) float         g_Xproj[(size_t)NB * NN * ND]; // 16.8 MB
static __device__ float2        g_l12[NN];

// ---------------- PTX helpers ----------------------------------------------
#define CP_ASYNC16(dst, src) \
    asm volatile("cp.async.cg.shared.global [%0], [%1], 16;" :: "r"(dst), "l"(src))
#define CP_COMMIT() asm volatile("cp.async.commit_group;" ::: "memory")
#define CP_WAIT(n)  asm volatile("cp.async.wait_group %0;" :: "n"(n) : "memory")

__device__ __forceinline__ uint32_t smem_u32(const void* p) {
    uint32_t a;
    asm("{ .reg .u64 t; cvta.to.shared.u64 t, %1; cvt.u32.u64 %0, t; }" : "=r"(a) : "l"(p));
    return a;
}
__device__ __forceinline__ void ldsm4(uint32_t a, uint32_t& r0, uint32_t& r1, uint32_t& r2, uint32_t& r3) {
    asm volatile("ldmatrix.sync.aligned.m8n8.x4.shared.b16 {%0,%1,%2,%3},[%4];"
                 : "=r"(r0), "=r"(r1), "=r"(r2), "=r"(r3) : "r"(a));
}
// non-volatile: pure register dataflow (ordering via data deps)
__device__ __forceinline__ void mma_bf16(float* c, uint32_t a0, uint32_t a1, uint32_t a2, uint32_t a3,
                                         uint32_t b0, uint32_t b1) {
    asm("mma.sync.aligned.m16n8k16.row.col.f32.bf16.bf16.f32 "
        "{%0,%1,%2,%3}, {%4,%5,%6,%7}, {%8,%9}, {%0,%1,%2,%3};"
        : "+f"(c[0]), "+f"(c[1]), "+f"(c[2]), "+f"(c[3])
        : "r"(a0), "r"(a1), "r"(a2), "r"(a3), "r"(b0), "r"(b1));
}
__device__ __forceinline__ uint32_t pack_bf2(float a, float b) {
    __nv_bfloat162 p = __floats2bfloat162_rn(a, b);
    return *(uint32_t*)&p;
}

// ---------------- kernel 1: threshold/scatter W, incidence_all, l1/l2 ------
// (best-measured version — scalar near-coalesced; prep is DRAM-bound, closed)
__global__ void k_prep(const float* __restrict__ inc, float* __restrict__ inc_all) {
    int i = blockIdx.x;
    const float* row = inc + (size_t)i * (NN - 1);
    float* orow = inc_all + (size_t)i * NN;
    __nv_bfloat16* wrow = g_Wbf + (size_t)i * NN;

    float lmax = 0.0f, lsq = 0.0f;
    for (int j = threadIdx.x; j < NN - 1; j += blockDim.x) {
        float v = row[j];
        float w = (v > 0.01f) ? v : 0.0f;
        int fc = j + (j >= i);
        orow[fc] = w;
        wrow[fc] = __float2bfloat16(w);
        lmax = fmaxf(lmax, w);
        lsq += w * w;
    }
    if (threadIdx.x == 0) {
        orow[i] = 1.0f;
        wrow[i] = __float2bfloat16(0.0f);
    }
    #pragma unroll
    for (int o = 16; o > 0; o >>= 1) {
        lmax = fmaxf(lmax, __shfl_xor_sync(0xffffffffu, lmax, o));
        lsq += __shfl_xor_sync(0xffffffffu, lsq, o);
    }
    __shared__ float sm[8], ss[8];
    int wid = threadIdx.x >> 5, lane = threadIdx.x & 31;
    if (lane == 0) { sm[wid] = lmax; ss[wid] = lsq; }
    __syncthreads();
    if (threadIdx.x == 0) {
        float m = sm[0], q = ss[0];
        #pragma unroll
        for (int k = 1; k < 8; k++) { m = fmaxf(m, sm[k]); q += ss[k]; }
        g_l12[i] = make_float2(m, sqrtf(q));
    }
}

// ---------------- kernel 2: fused Xt transpose + X_proj --------------------
// blocks [0,1024): transpose X -> Xt bf16 [b*64+d][k]
// blocks [1024,1280): X_proj = X @ r_proj, 4-row-blocked
#define XS 68
__global__ void __launch_bounds__(256) k_xtp(const float* __restrict__ X,
                                             const float* __restrict__ rp) {
    __shared__ __align__(16) float s[64 * XS];   // 17408B; xproj uses first 16KB
    const int tid = threadIdx.x;

    if (blockIdx.x < 1024) {
        // ---- xt tile ----
        const int idx = blockIdx.x;
        const int k0 = (idx & 63) * 64;
        const int b  = idx >> 6;
        {
            int tr = tid >> 2, tc = (tid & 3) * 16;
            const float* src = X + ((size_t)b * NN + k0 + tr) * ND + tc;
            float4 v0 = ((const float4*)src)[0];
            float4 v1 = ((const float4*)src)[1];
            float4 v2 = ((const float4*)src)[2];
            float4 v3 = ((const float4*)src)[3];
            float* sr = s + tr * XS + tc;
            *(float4*)(sr + 0)  = v0;
            *(float4*)(sr + 4)  = v1;
            *(float4*)(sr + 8)  = v2;
            *(float4*)(sr + 12) = v3;
        }
        __syncthreads();
        {
            int d = tid >> 2, kc = (tid & 3) * 16;
            const float* sc = s + kc * XS + d;
            uint4 u0, u1;
            u0.x = pack_bf2(sc[0 * XS],  sc[1 * XS]);
            u0.y = pack_bf2(sc[2 * XS],  sc[3 * XS]);
            u0.z = pack_bf2(sc[4 * XS],  sc[5 * XS]);
            u0.w = pack_bf2(sc[6 * XS],  sc[7 * XS]);
            u1.x = pack_bf2(sc[8 * XS],  sc[9 * XS]);
            u1.y = pack_bf2(sc[10 * XS], sc[11 * XS]);
            u1.z = pack_bf2(sc[12 * XS], sc[13 * XS]);
            u1.w = pack_bf2(sc[14 * XS], sc[15 * XS]);
            __nv_bfloat16* dst = g_Xt + ((size_t)b * ND + d) * NN + k0 + kc;
            ((uint4*)dst)[0] = u0;
            ((uint4*)dst)[1] = u1;
        }
    } else {
        // ---- xproj chunk (4-row x 16-col blocks per thread) ----
        float* rps = s;
        for (int t = tid; t < ND * ND / 4; t += 256)
            ((float4*)rps)[t] = ((const float4*)rp)[t];
        __syncthreads();

        const int gt = (blockIdx.x - 1024) * 256 + tid;   // 65536 threads
        const int rg = gt >> 2;
        const int d0 = (gt & 3) * 16;
        const int r0 = rg * 4;
        const float* xr = X + (size_t)r0 * ND;

        float acc[4][16];
        #pragma unroll
        for (int i = 0; i < 4; i++)
            #pragma unroll
            for (int j = 0; j < 16; j++) acc[i][j] = 0.0f;

        #pragma unroll 2
        for (int e4 = 0; e4 < ND; e4 += 4) {
            float4 xv[4];
            #pragma unroll
            for (int i = 0; i < 4; i++)
                xv[i] = *(const float4*)(xr + i * ND + e4);

            #pragma unroll
            for (int ee = 0; ee < 4; ee++) {
                const float* rr = rps + (e4 + ee) * ND + d0;
                float4 rv0 = ((const float4*)rr)[0];
                float4 rv1 = ((const float4*)rr)[1];
                float4 rv2 = ((const float4*)rr)[2];
                float4 rv3 = ((const float4*)rr)[3];
                #pragma unroll
                for (int i = 0; i < 4; i++) {
                    const float xe = (ee == 0) ? xv[i].x : (ee == 1) ? xv[i].y
                                   : (ee == 2) ? xv[i].z : xv[i].w;
                    acc[i][0]  += xe * rv0.x;  acc[i][1]  += xe * rv0.y;
                    acc[i][2]  += xe * rv0.z;  acc[i][3]  += xe * rv0.w;
                    acc[i][4]  += xe * rv1.x;  acc[i][5]  += xe * rv1.y;
                    acc[i][6]  += xe * rv1.z;  acc[i][7]  += xe * rv1.w;
                    acc[i][8]  += xe * rv2.x;  acc[i][9]  += xe * rv2.y;
                    acc[i][10] += xe * rv2.z;  acc[i][11] += xe * rv2.w;
                    acc[i][12] += xe * rv3.x;  acc[i][13] += xe * rv3.y;
                    acc[i][14] += xe * rv3.z;  acc[i][15] += xe * rv3.w;
                }
            }
        }

        #pragma unroll
        for (int i = 0; i < 4; i++) {
            float* o = g_Xproj + (size_t)(r0 + i) * ND + d0;
            #pragma unroll
            for (int q = 0; q < 4; q++)
                ((float4*)o)[q] = make_float4(acc[i][4*q], acc[i][4*q+1],
                                              acc[i][4*q+2], acc[i][4*q+3]);
        }
    }
}

// ---------------- kernel 3: HMMA GEMM (fused N=1024) + loss epilogue -------
// 512 threads, 16 warps 4x4 (warp tile 64x32); BM=256, occ 1, 128-CTA uniform
// wave; 4-stage cp.async pipeline (WAIT(2) -> 2 completed stages of slack).
__global__ void __launch_bounds__(512, 1) k_gemm(float* __restrict__ out_loss) {
    extern __shared__ char dsm[];
    const uint32_t sbase = smem_u32(dsm);

    const int tid = threadIdx.x, wid = tid >> 5, lane = tid & 31;
    const int wm = wid >> 2, wn = wid & 3;           // 4x4 warps, 64x32 each
    const int mbase = wm * 64, nbase = wn * 32;
    const int g = lane >> 2, t4 = lane & 3;
    const int lrow = lane & 15, lcol = (lane >> 4) * 8;

    const int m0 = blockIdx.x * BM;
    const int n0 = blockIdx.y * BN;                  // n = b*64+d space

    const __nv_bfloat16* Ag = g_Wbf + (size_t)m0 * NN;
    const __nv_bfloat16* Bg = g_Xt + (size_t)n0 * NN;

    const int ldrow = tid >> 3;            // 0..63 (+64i)
    const int ldcol = (tid & 7) * 8;       // 0..56
    const uint32_t ld_off = (uint32_t)(ldrow * (ASTR * 2) + ldcol * 2);

    const uint32_t a_inv = (uint32_t)((mbase + lrow) * (ASTR * 2) + lcol * 2);
    const uint32_t b_inv = (uint32_t)((nbase + lrow) * (ASTR * 2) + lcol * 2) + A_TILE_B;

    #define LOAD_STAGE(sb_, kc_) do {                                        \
        const __nv_bfloat16* _ag = Ag + (size_t)(kc_) * BK + ldcol;          \
        const __nv_bfloat16* _bg = Bg + (size_t)(kc_) * BK + ldcol;          \
        _Pragma("unroll")                                                    \
        for (int _i = 0; _i < 4; _i++) {                                     \
            uint32_t _o = ld_off + (uint32_t)(_i * 64 * (ASTR * 2));         \
            CP_ASYNC16((sb_) + _o, _ag + (size_t)(ldrow + _i * 64) * NN);    \
        }                                                                    \
        _Pragma("unroll")                                                    \
        for (int _i = 0; _i < 2; _i++) {                                     \
            uint32_t _o = ld_off + (uint32_t)(_i * 64 * (ASTR * 2));         \
            CP_ASYNC16((sb_) + A_TILE_B + _o,                                \
                       _bg + (size_t)(ldrow + _i * 64) * NN);                \
        }                                                                    \
        CP_COMMIT();                                                         \
    } while (0)

    float acc[4][4][4];
    #pragma unroll
    for (int i = 0; i < 4; i++)
        #pragma unroll
        for (int j = 0; j < 4; j++)
            #pragma unroll
            for (int k = 0; k < 4; k++) acc[i][j][k] = 0.0f;

    LOAD_STAGE(sbase, 0);
    LOAD_STAGE(sbase + STAGE_B, 1);
    LOAD_STAGE(sbase + 2 * STAGE_B, 2);

    uint32_t soff = 0;
    uint32_t poff = 3 * STAGE_B;
    #pragma unroll 1
    for (int kt = 0; kt < KT; kt++) {
        CP_WAIT(2);                      // committed = 3+kt; <=2 pending => g_kt done
        __syncthreads();

        if (kt + 3 < KT) LOAD_STAGE(sbase + poff, kt + 3);
        else CP_COMMIT();                // keep group-count invariant

        const uint32_t ab = sbase + soff + a_inv;
        const uint32_t bb = sbase + soff + b_inv;
        #pragma unroll
        for (int ks = 0; ks < 4; ks++) {
            const uint32_t kb = (uint32_t)(ks * 32);
            uint32_t ar[4][4], br[2][4];
            #pragma unroll
            for (int mf = 0; mf < 4; mf++)
                ldsm4(ab + kb + (uint32_t)(mf * 16 * (ASTR * 2)),
                      ar[mf][0], ar[mf][1], ar[mf][2], ar[mf][3]);
            #pragma unroll
            for (int p = 0; p < 2; p++)
                ldsm4(bb + kb + (uint32_t)(p * 16 * (ASTR * 2)),
                      br[p][0], br[p][1], br[p][2], br[p][3]);
            #pragma unroll
            for (int mf = 0; mf < 4; mf++)
                #pragma unroll
                for (int p = 0; p < 2; p++) {
                    mma_bf16(acc[mf][2 * p + 0], ar[mf][0], ar[mf][1], ar[mf][2], ar[mf][3],
                             br[p][0], br[p][2]);
                    mma_bf16(acc[mf][2 * p + 1], ar[mf][0], ar[mf][1], ar[mf][2], ar[mf][3],
                             br[p][1], br[p][3]);
                }
        }

        soff += STAGE_B; if (soff == STAGES * STAGE_B) soff = 0;
        poff += STAGE_B; if (poff == STAGES * STAGE_B) poff = 0;
    }

    // ---- epilogue: warp covers rows mbase..+63, cols nbase..+31 ----
    const int b = (n0 + nbase) >> 6;
    const int dbase = nbase & 63;
    float rs[8];
    #pragma unroll
    for (int i = 0; i < 8; i++) rs[i] = 0.0f;

    #pragma unroll
    for (int mf = 0; mf < 4; mf++) {
        #pragma unroll
        for (int h = 0; h < 2; h++) {
            const int r = m0 + mbase + mf * 16 + h * 8 + g;
            const float* xp = g_Xproj + ((size_t)b * NN + r) * ND + dbase;
            float a = 0.0f;
            #pragma unroll
            for (int nf = 0; nf < 4; nf++) {
                float2 v = *(const float2*)(xp + nf * 8 + 2 * t4);
                float d0 = v.x - acc[mf][nf][h * 2 + 0];
                float d1 = v.y - acc[mf][nf][h * 2 + 1];
                a += d0 * d0 + d1 * d1;
            }
            rs[mf * 2 + h] = a;
        }
    }
    #pragma unroll
    for (int i = 0; i < 8; i++) {
        rs[i] += __shfl_xor_sync(0xffffffffu, rs[i], 1);
        rs[i] += __shfl_xor_sync(0xffffffffu, rs[i], 2);
    }

    __syncthreads();
    float* red = (float*)dsm;       // [wm=4][wn=4][64]
    if (t4 == 0) {
        #pragma unroll
        for (int i = 0; i < 8; i++) {
            const int rloc = (i >> 1) * 16 + (i & 1) * 8 + g;
            red[(wm * 4 + wn) * 64 + rloc] = rs[i];
        }
    }
    __syncthreads();
    {
        const int bsel = tid >> 8;            // 0,1: batch within tile
        const int rl = tid & 255;             // row within BM=256
        const int wmx = rl >> 6, rloc = rl & 63;
        const float s2 = red[(wmx * 4 + bsel * 2) * 64 + rloc] +
                         red[(wmx * 4 + bsel * 2 + 1) * 64 + rloc];
        const int row = m0 + rl;
        const int batch = blockIdx.y * 2 + bsel;
        const float2 l = g_l12[row];
        out_loss[(size_t)batch * NN + row] = 0.2f * sqrtf(s2) + l.x + 0.001f * l.y;
    }
}

// ---------------- launch ----------------------------------------------------
extern "C" void kernel_launch(void* const* d_in, const int* in_sizes, int n_in,
                              void* d_out, int out_size) {
    const float *X = nullptr, *rp = nullptr, *inc = nullptr;
    for (int i = 0; i < n_in; i++) {
        if (in_sizes[i] == NB * NN * ND)       X   = (const float*)d_in[i];
        else if (in_sizes[i] == ND * ND)       rp  = (const float*)d_in[i];
        else if (in_sizes[i] == NN * (NN - 1)) inc = (const float*)d_in[i];
    }
    float* out = (float*)d_out;
    float* loss = out;                           // [B, N]
    float* inc_all = out + (size_t)NB * NN;      // [N, N]

    cudaFuncSetAttribute(k_gemm, cudaFuncAttributeMaxDynamicSharedMemorySize, SMEM_B);

    k_prep<<<NN, 256>>>(inc, inc_all);
    k_xtp<<<1024 + 256, 256>>>(X, rp);
    k_gemm<<<dim3(NN / BM, (NB * ND) / BN), 512, SMEM_B>>>(loss);
}